// round 2
// baseline (speedup 1.0000x reference)
#include <cuda_runtime.h>
#include <cuda_bf16.h>
#include <cstdint>

// Problem constants
#define BB 4
#define TT 2048
#define CC 1024
#define HH 16
#define DD 64
#define BT (BB*TT)          // 8192
#define TILE 64             // q/k tile rows in attention

// ---------------------------------------------------------------------------
// Scratch (allocations are forbidden -> __device__ globals). 4 x 32MB.
// ---------------------------------------------------------------------------
__device__ float g_q[(size_t)BT * CC];
__device__ float g_k[(size_t)BT * CC];
__device__ float g_v[(size_t)BT * CC];
__device__ float g_y[(size_t)BT * CC];

// ---------------------------------------------------------------------------
// GEMM: out[m][n] = sum_k A[m][k] * W[n][k] + bias[n]
// (torch Linear convention: y = x @ W^T + b, W is [out,in] row-major)
// BM=BN=64, BK=16, 256 threads, 4x4 outputs/thread, fp32.
// qkv variant: blockIdx.z in {0,1,2} selects (Wq,bq,g_q)/(Wk,bk,g_k)/(Wv,bv,g_v)
// ---------------------------------------------------------------------------
__device__ __forceinline__
void gemm_body(const float* __restrict__ A, const float* __restrict__ W,
               const float* __restrict__ bias, float* __restrict__ out,
               int M, int N, int K) {
    __shared__ float As[16][68];   // [k][m], padded (68*4=272B rows)
    __shared__ float Bs[16][68];   // [k][n]

    const int bn = blockIdx.x * 64;
    const int bm = blockIdx.y * 64;
    const int tid = threadIdx.x;
    const int tx = tid & 15;
    const int ty = tid >> 4;
    const int rm = ty * 4;
    const int rn = tx * 4;

    float c[4][4];
#pragma unroll
    for (int i = 0; i < 4; i++)
#pragma unroll
        for (int j = 0; j < 4; j++) c[i][j] = 0.0f;

    for (int k0 = 0; k0 < K; k0 += 16) {
        __syncthreads();
#pragma unroll
        for (int i = 0; i < 4; i++) {
            int idx = tid + i * 256;        // 0..1023 covers 64 rows x 16 k
            int mm = idx >> 4;
            int kk = idx & 15;
            As[kk][mm] = A[(size_t)(bm + mm) * K + k0 + kk];
            Bs[kk][mm] = W[(size_t)(bn + mm) * K + k0 + kk];
        }
        __syncthreads();
#pragma unroll
        for (int kk = 0; kk < 16; kk++) {
            float4 a = *(const float4*)&As[kk][rm];
            float4 b = *(const float4*)&Bs[kk][rn];
            c[0][0] += a.x * b.x; c[0][1] += a.x * b.y; c[0][2] += a.x * b.z; c[0][3] += a.x * b.w;
            c[1][0] += a.y * b.x; c[1][1] += a.y * b.y; c[1][2] += a.y * b.z; c[1][3] += a.y * b.w;
            c[2][0] += a.z * b.x; c[2][1] += a.z * b.y; c[2][2] += a.z * b.z; c[2][3] += a.z * b.w;
            c[3][0] += a.w * b.x; c[3][1] += a.w * b.y; c[3][2] += a.w * b.z; c[3][3] += a.w * b.w;
        }
    }

    float bb0 = bias[bn + rn + 0];
    float bb1 = bias[bn + rn + 1];
    float bb2 = bias[bn + rn + 2];
    float bb3 = bias[bn + rn + 3];
#pragma unroll
    for (int i = 0; i < 4; i++) {
        float4 o;
        o.x = c[i][0] + bb0; o.y = c[i][1] + bb1;
        o.z = c[i][2] + bb2; o.w = c[i][3] + bb3;
        *(float4*)&out[(size_t)(bm + rm + i) * N + bn + rn] = o;
    }
}

__global__ __launch_bounds__(256)
void gemm_qkv_kernel(const float* __restrict__ x,
                     const float* __restrict__ Wq, const float* __restrict__ bq,
                     const float* __restrict__ Wk, const float* __restrict__ bk,
                     const float* __restrict__ Wv, const float* __restrict__ bv) {
    const float* W; const float* b; float* o;
    if (blockIdx.z == 0)      { W = Wq; b = bq; o = g_q; }
    else if (blockIdx.z == 1) { W = Wk; b = bk; o = g_k; }
    else                      { W = Wv; b = bv; o = g_v; }
    gemm_body(x, W, b, o, BT, CC, CC);
}

__global__ __launch_bounds__(256)
void gemm_out_kernel(const float* __restrict__ Wp, const float* __restrict__ bp,
                     float* __restrict__ out) {
    gemm_body(g_y, Wp, bp, out, BT, CC, CC);
}

// ---------------------------------------------------------------------------
// Flash attention (fp32, online softmax, causal, tile skipping).
// grid = (T/64, H, B); block = 256 threads.
// Each row of the 64-row Q tile is owned by 4 consecutive threads,
// each thread holding a 16-wide slice of the head dim (D=64).
// ---------------------------------------------------------------------------
__global__ __launch_bounds__(256)
void attn_kernel() {
    const float* __restrict__ q = g_q;
    const float* __restrict__ k = g_k;
    const float* __restrict__ v = g_v;

    const int qi = blockIdx.x;       // q tile index (0..31)
    const int h  = blockIdx.y;
    const int b  = blockIdx.z;
    const int tid = threadIdx.x;
    const int row = tid >> 2;        // 0..63 (row within tile)
    const int dpart = (tid & 3) * 16;

    __shared__ float Ks[TILE][DD];         // 16 KB
    __shared__ float Vs[TILE][DD];         // 16 KB
    __shared__ float Ss[TILE][TILE];       // 16 KB, indexed [j][row]

    const int qrow_g = qi * TILE + row;
    const float* qbase = q + ((size_t)(b * TT + qrow_g)) * CC + h * DD + dpart;
    float qreg[16];
#pragma unroll
    for (int dd = 0; dd < 16; dd++) qreg[dd] = qbase[dd];

    float m = -1e30f, l = 0.0f;
    float acc[16];
#pragma unroll
    for (int dd = 0; dd < 16; dd++) acc[dd] = 0.0f;

    const float scale = 0.125f;      // 1/sqrt(64)

    for (int kt = 0; kt <= qi; kt++) {
        __syncthreads();
        // cooperative load of K,V tiles (rows kt*64.., head column block)
        for (int i = tid; i < TILE * DD; i += 256) {
            int r = i >> 6;
            int cidx = i & 63;
            size_t gidx = ((size_t)(b * TT + kt * TILE + r)) * CC + h * DD + cidx;
            Ks[r][cidx] = k[gidx];
            Vs[r][cidx] = v[gidx];
        }
        __syncthreads();

        const bool diag = (kt == qi);
        // scores: S[j][row] = scale * dot(Q[row], K[j]) with causal mask
        for (int j = 0; j < TILE; j++) {
            const float4* Krow = (const float4*)&Ks[j][dpart];
            float s = 0.0f;
#pragma unroll
            for (int c4 = 0; c4 < 4; c4++) {
                float4 kv = Krow[c4];
                s += qreg[c4 * 4 + 0] * kv.x + qreg[c4 * 4 + 1] * kv.y
                   + qreg[c4 * 4 + 2] * kv.z + qreg[c4 * 4 + 3] * kv.w;
            }
            s += __shfl_xor_sync(0xffffffffu, s, 1);
            s += __shfl_xor_sync(0xffffffffu, s, 2);
            if ((tid & 3) == 0) {
                float sv = s * scale;
                if (diag && j > row) sv = -1e30f;
                Ss[j][row] = sv;
            }
        }
        __syncwarp();  // writers/readers of each Ss row are in the same warp

        // online softmax update
        float mt = m;
#pragma unroll 8
        for (int j = 0; j < TILE; j++) mt = fmaxf(mt, Ss[j][row]);
        float alpha = __expf(m - mt);
        l *= alpha;
#pragma unroll
        for (int dd = 0; dd < 16; dd++) acc[dd] *= alpha;

        for (int j = 0; j < TILE; j++) {
            float p = __expf(Ss[j][row] - mt);
            l += p;
            const float4* Vrow = (const float4*)&Vs[j][dpart];
#pragma unroll
            for (int c4 = 0; c4 < 4; c4++) {
                float4 vv = Vrow[c4];
                acc[c4 * 4 + 0] += p * vv.x;
                acc[c4 * 4 + 1] += p * vv.y;
                acc[c4 * 4 + 2] += p * vv.z;
                acc[c4 * 4 + 3] += p * vv.w;
            }
        }
        m = mt;
        __syncwarp();  // done reading Ss before next iteration's writes
    }

    const float inv = 1.0f / l;
    float* ybase = g_y + ((size_t)(b * TT + qrow_g)) * CC + h * DD + dpart;
#pragma unroll
    for (int c4 = 0; c4 < 4; c4++) {
        float4 o;
        o.x = acc[c4 * 4 + 0] * inv;
        o.y = acc[c4 * 4 + 1] * inv;
        o.z = acc[c4 * 4 + 2] * inv;
        o.w = acc[c4 * 4 + 3] * inv;
        *(float4*)&ybase[c4 * 4] = o;
    }
}

// ---------------------------------------------------------------------------
// Launch
// ---------------------------------------------------------------------------
extern "C" void kernel_launch(void* const* d_in, const int* in_sizes, int n_in,
                              void* d_out, int out_size) {
    const float* x  = (const float*)d_in[0];
    const float* Wq = (const float*)d_in[1];
    const float* bq = (const float*)d_in[2];
    const float* Wk = (const float*)d_in[3];
    const float* bk = (const float*)d_in[4];
    const float* Wv = (const float*)d_in[5];
    const float* bv = (const float*)d_in[6];
    const float* Wp = (const float*)d_in[7];
    const float* bp = (const float*)d_in[8];
    float* out = (float*)d_out;

    dim3 gqkv(CC / 64, BT / 64, 3);    // (16, 128, 3)
    gemm_qkv_kernel<<<gqkv, 256>>>(x, Wq, bq, Wk, bk, Wv, bv);

    attn_kernel<<<dim3(TT / TILE, HH, BB), 256>>>();

    dim3 gout(CC / 64, BT / 64);       // (16, 128)
    gemm_out_kernel<<<gout, 256>>>(Wp, bp, out);
}

// round 3
// speedup vs baseline: 13.2460x; 13.2460x over previous
#include <cuda_runtime.h>
#include <cuda_fp16.h>
#include <cstdint>

// Problem constants
#define BB 4
#define TT 2048
#define CC 1024
#define HH 16
#define DD 64
#define BT (BB*TT)          // 8192

// ---------------------------------------------------------------------------
// Scratch (__device__ globals; allocations forbidden)
// ---------------------------------------------------------------------------
__device__ __half g_hx[(size_t)BT * CC];
__device__ __half g_hq[(size_t)BT * CC];
__device__ __half g_hk[(size_t)BT * CC];
__device__ __half g_hv[(size_t)BT * CC];
__device__ __half g_hy[(size_t)BT * CC];
__device__ __half g_hWq[(size_t)CC * CC];
__device__ __half g_hWk[(size_t)CC * CC];
__device__ __half g_hWv[(size_t)CC * CC];
__device__ __half g_hWp[(size_t)CC * CC];

// ---------------------------------------------------------------------------
// PTX helpers
// ---------------------------------------------------------------------------
__device__ __forceinline__ uint32_t smem_u32(const void* p) {
    return (uint32_t)__cvta_generic_to_shared(p);
}
__device__ __forceinline__ void ldm4(uint32_t (&r)[4], uint32_t addr) {
    asm volatile("ldmatrix.sync.aligned.m8n8.x4.shared.b16 {%0,%1,%2,%3}, [%4];"
                 : "=r"(r[0]), "=r"(r[1]), "=r"(r[2]), "=r"(r[3]) : "r"(addr));
}
__device__ __forceinline__ void ldm4t(uint32_t (&r)[4], uint32_t addr) {
    asm volatile("ldmatrix.sync.aligned.m8n8.x4.trans.shared.b16 {%0,%1,%2,%3}, [%4];"
                 : "=r"(r[0]), "=r"(r[1]), "=r"(r[2]), "=r"(r[3]) : "r"(addr));
}
__device__ __forceinline__ void mma16816(float (&c)[4], const uint32_t (&a)[4],
                                         uint32_t b0, uint32_t b1) {
    asm volatile(
        "mma.sync.aligned.m16n8k16.row.col.f32.f16.f16.f32 "
        "{%0,%1,%2,%3}, {%4,%5,%6,%7}, {%8,%9}, {%0,%1,%2,%3};"
        : "+f"(c[0]), "+f"(c[1]), "+f"(c[2]), "+f"(c[3])
        : "r"(a[0]), "r"(a[1]), "r"(a[2]), "r"(a[3]), "r"(b0), "r"(b1));
}
__device__ __forceinline__ uint32_t packh2(float x, float y) {
    __half2 h = __floats2half2_rn(x, y);
    return *(uint32_t*)&h;
}

// ---------------------------------------------------------------------------
// fp32 -> fp16 conversion
// ---------------------------------------------------------------------------
__global__ void f2h_kernel(const float4* __restrict__ in, __half2* __restrict__ out, int n4) {
    int i = blockIdx.x * blockDim.x + threadIdx.x;
    if (i < n4) {
        float4 v = in[i];
        out[2 * i + 0] = __floats2half2_rn(v.x, v.y);
        out[2 * i + 1] = __floats2half2_rn(v.z, v.w);
    }
}

// ---------------------------------------------------------------------------
// HGEMM: out[m][n] = sum_k A[m][k] * W[n][k] + bias[n]
// BM=BN=128, BK=32, 256 threads (8 warps, 64x32 warp tile), fp32 accum.
// smem stride 40 halfs (80B) -> conflict-free stores + ldmatrix.
// ---------------------------------------------------------------------------
template<bool HALF_OUT>
__device__ __forceinline__
void hgemm_body(const __half* __restrict__ A, const __half* __restrict__ W,
                const float* __restrict__ bias, void* __restrict__ out) {
    __shared__ __half sA[128 * 40];
    __shared__ __half sB[128 * 40];

    const int tid = threadIdx.x;
    const int lane = tid & 31;
    const int w = tid >> 5;
    const int bm = blockIdx.y * 128;
    const int bn = blockIdx.x * 128;
    const int wm = (w & 1) * 64;
    const int wn = (w >> 1) * 32;

    float c[4][4][4];
#pragma unroll
    for (int mf = 0; mf < 4; mf++)
#pragma unroll
        for (int nf = 0; nf < 4; nf++)
#pragma unroll
            for (int j = 0; j < 4; j++) c[mf][nf][j] = 0.0f;

    for (int k0 = 0; k0 < CC; k0 += 32) {
        __syncthreads();
#pragma unroll
        for (int i = 0; i < 2; i++) {
            int ci = tid + i * 256;
            int row = ci >> 2;
            int sub = ci & 3;
            *(uint4*)&sA[row * 40 + sub * 8] =
                *(const uint4*)&A[(size_t)(bm + row) * CC + k0 + sub * 8];
            *(uint4*)&sB[row * 40 + sub * 8] =
                *(const uint4*)&W[(size_t)(bn + row) * CC + k0 + sub * 8];
        }
        __syncthreads();
#pragma unroll
        for (int g = 0; g < 2; g++) {
            uint32_t a[4][4];
#pragma unroll
            for (int mf = 0; mf < 4; mf++) {
                uint32_t addr = smem_u32(&sA[(wm + mf * 16 + (lane & 15)) * 40 + g * 16 + (lane >> 4) * 8]);
                ldm4(a[mf], addr);
            }
            uint32_t b[4][2];
#pragma unroll
            for (int nf2 = 0; nf2 < 2; nf2++) {
                uint32_t r[4];
                uint32_t addr = smem_u32(&sB[(wn + nf2 * 16 + (lane & 15)) * 40 + g * 16 + (lane >> 4) * 8]);
                ldm4(r, addr);
                b[nf2 * 2 + 0][0] = r[0]; b[nf2 * 2 + 0][1] = r[2];
                b[nf2 * 2 + 1][0] = r[1]; b[nf2 * 2 + 1][1] = r[3];
            }
#pragma unroll
            for (int mf = 0; mf < 4; mf++)
#pragma unroll
                for (int nf = 0; nf < 4; nf++)
                    mma16816(c[mf][nf], a[mf], b[nf][0], b[nf][1]);
        }
    }

#pragma unroll
    for (int mf = 0; mf < 4; mf++) {
        int r0 = bm + wm + mf * 16 + (lane >> 2);
        int r1 = r0 + 8;
#pragma unroll
        for (int nf = 0; nf < 4; nf++) {
            int col = bn + wn + nf * 8 + (lane & 3) * 2;
            float b0 = bias[col], b1 = bias[col + 1];
            if (HALF_OUT) {
                __half* o = (__half*)out;
                *(__half2*)&o[(size_t)r0 * CC + col] = __floats2half2_rn(c[mf][nf][0] + b0, c[mf][nf][1] + b1);
                *(__half2*)&o[(size_t)r1 * CC + col] = __floats2half2_rn(c[mf][nf][2] + b0, c[mf][nf][3] + b1);
            } else {
                float* o = (float*)out;
                float2 v0 = make_float2(c[mf][nf][0] + b0, c[mf][nf][1] + b1);
                float2 v1 = make_float2(c[mf][nf][2] + b0, c[mf][nf][3] + b1);
                *(float2*)&o[(size_t)r0 * CC + col] = v0;
                *(float2*)&o[(size_t)r1 * CC + col] = v1;
            }
        }
    }
}

__global__ __launch_bounds__(256)
void hgemm_qkv_kernel(const float* __restrict__ bq, const float* __restrict__ bk,
                      const float* __restrict__ bv) {
    if (blockIdx.z == 0)      hgemm_body<true>(g_hx, g_hWq, bq, g_hq);
    else if (blockIdx.z == 1) hgemm_body<true>(g_hx, g_hWk, bk, g_hk);
    else                      hgemm_body<true>(g_hx, g_hWv, bv, g_hv);
}

__global__ __launch_bounds__(256)
void hgemm_out_kernel(const float* __restrict__ bp, float* __restrict__ out) {
    hgemm_body<false>(g_hy, g_hWp, bp, out);
}

// ---------------------------------------------------------------------------
// Flash attention, fp16 tensor cores, fp32 online softmax.
// grid = (T/64, H, B), block = 128 threads (4 warps x 16 Q rows).
// ---------------------------------------------------------------------------
__global__ __launch_bounds__(128)
void attn_kernel() {
    const int qi = blockIdx.x;
    const int h  = blockIdx.y;
    const int b  = blockIdx.z;
    const int tid = threadIdx.x;
    const int lane = tid & 31;
    const int w = tid >> 5;

    __shared__ __half sQ[64 * 72];
    __shared__ __half sK[64 * 72];
    __shared__ __half sV[64 * 72];

    // load Q tile (64 x 64 halfs)
    const __half* qg = g_hq + ((size_t)(b * TT + qi * 64)) * CC + h * DD;
#pragma unroll
    for (int i = 0; i < 4; i++) {
        int ci = tid + i * 128;
        int row = ci >> 3, sub = ci & 7;
        *(uint4*)&sQ[row * 72 + sub * 8] = *(const uint4*)&qg[(size_t)row * CC + sub * 8];
    }
    __syncthreads();

    uint32_t qa[4][4];
#pragma unroll
    for (int g = 0; g < 4; g++) {
        uint32_t addr = smem_u32(&sQ[(w * 16 + (lane & 15)) * 72 + g * 16 + (lane >> 4) * 8]);
        ldm4(qa[g], addr);
    }

    float m0 = -1e30f, m1 = -1e30f, l0 = 0.0f, l1 = 0.0f;
    float o[8][4];
#pragma unroll
    for (int nf = 0; nf < 8; nf++)
#pragma unroll
        for (int j = 0; j < 4; j++) o[nf][j] = 0.0f;

    const int rbase = w * 16 + (lane >> 2);   // local row (row0); row1 = rbase+8

    for (int kt = 0; kt <= qi; kt++) {
        __syncthreads();
        const __half* kg = g_hk + ((size_t)(b * TT + kt * 64)) * CC + h * DD;
        const __half* vg = g_hv + ((size_t)(b * TT + kt * 64)) * CC + h * DD;
#pragma unroll
        for (int i = 0; i < 4; i++) {
            int ci = tid + i * 128;
            int row = ci >> 3, sub = ci & 7;
            *(uint4*)&sK[row * 72 + sub * 8] = *(const uint4*)&kg[(size_t)row * CC + sub * 8];
            *(uint4*)&sV[row * 72 + sub * 8] = *(const uint4*)&vg[(size_t)row * CC + sub * 8];
        }
        __syncthreads();

        // S = Q @ K^T  (f32 accum)
        float s[8][4];
#pragma unroll
        for (int nf = 0; nf < 8; nf++)
#pragma unroll
            for (int j = 0; j < 4; j++) s[nf][j] = 0.0f;

#pragma unroll
        for (int g = 0; g < 4; g++) {
#pragma unroll
            for (int nf2 = 0; nf2 < 4; nf2++) {
                uint32_t r[4];
                uint32_t addr = smem_u32(&sK[(nf2 * 16 + (lane & 15)) * 72 + g * 16 + (lane >> 4) * 8]);
                ldm4(r, addr);
                mma16816(s[nf2 * 2 + 0], qa[g], r[0], r[2]);
                mma16816(s[nf2 * 2 + 1], qa[g], r[1], r[3]);
            }
        }

        // scale + causal mask (diag tile only; tile-local compare valid since kt==qi)
        const bool diag = (kt == qi);
#pragma unroll
        for (int nf = 0; nf < 8; nf++) {
            int col = nf * 8 + (lane & 3) * 2;
#pragma unroll
            for (int j = 0; j < 4; j++) s[nf][j] *= 0.125f;
            if (diag) {
                if (col + 0 > rbase)     s[nf][0] = -1e30f;
                if (col + 1 > rbase)     s[nf][1] = -1e30f;
                if (col + 0 > rbase + 8) s[nf][2] = -1e30f;
                if (col + 1 > rbase + 8) s[nf][3] = -1e30f;
            }
        }

        // row max across 4 lanes of the quad
        float mx0 = -1e30f, mx1 = -1e30f;
#pragma unroll
        for (int nf = 0; nf < 8; nf++) {
            mx0 = fmaxf(mx0, fmaxf(s[nf][0], s[nf][1]));
            mx1 = fmaxf(mx1, fmaxf(s[nf][2], s[nf][3]));
        }
        mx0 = fmaxf(mx0, __shfl_xor_sync(0xffffffffu, mx0, 1));
        mx0 = fmaxf(mx0, __shfl_xor_sync(0xffffffffu, mx0, 2));
        mx1 = fmaxf(mx1, __shfl_xor_sync(0xffffffffu, mx1, 1));
        mx1 = fmaxf(mx1, __shfl_xor_sync(0xffffffffu, mx1, 2));

        float mn0 = fmaxf(m0, mx0);
        float mn1 = fmaxf(m1, mx1);
        float alpha0 = __expf(m0 - mn0);
        float alpha1 = __expf(m1 - mn1);

        float ls0 = 0.0f, ls1 = 0.0f;
#pragma unroll
        for (int nf = 0; nf < 8; nf++) {
            s[nf][0] = __expf(s[nf][0] - mn0); ls0 += s[nf][0];
            s[nf][1] = __expf(s[nf][1] - mn0); ls0 += s[nf][1];
            s[nf][2] = __expf(s[nf][2] - mn1); ls1 += s[nf][2];
            s[nf][3] = __expf(s[nf][3] - mn1); ls1 += s[nf][3];
        }
        ls0 += __shfl_xor_sync(0xffffffffu, ls0, 1);
        ls0 += __shfl_xor_sync(0xffffffffu, ls0, 2);
        ls1 += __shfl_xor_sync(0xffffffffu, ls1, 1);
        ls1 += __shfl_xor_sync(0xffffffffu, ls1, 2);

        l0 = l0 * alpha0 + ls0;
        l1 = l1 * alpha1 + ls1;
        m0 = mn0; m1 = mn1;

#pragma unroll
        for (int nf = 0; nf < 8; nf++) {
            o[nf][0] *= alpha0; o[nf][1] *= alpha0;
            o[nf][2] *= alpha1; o[nf][3] *= alpha1;
        }

        // O += P @ V
#pragma unroll
        for (int g = 0; g < 4; g++) {
            uint32_t pa[4];
            pa[0] = packh2(s[2 * g + 0][0], s[2 * g + 0][1]);
            pa[1] = packh2(s[2 * g + 0][2], s[2 * g + 0][3]);
            pa[2] = packh2(s[2 * g + 1][0], s[2 * g + 1][1]);
            pa[3] = packh2(s[2 * g + 1][2], s[2 * g + 1][3]);
#pragma unroll
            for (int ng = 0; ng < 4; ng++) {
                uint32_t r[4];
                uint32_t addr = smem_u32(&sV[(g * 16 + (lane & 15)) * 72 + ng * 16 + (lane >> 4) * 8]);
                ldm4t(r, addr);
                mma16816(o[ng * 2 + 0], pa, r[0], r[1]);
                mma16816(o[ng * 2 + 1], pa, r[2], r[3]);
            }
        }
    }

    const float inv0 = 1.0f / l0;
    const float inv1 = 1.0f / l1;
    __half* yg = g_hy + ((size_t)(b * TT + qi * 64)) * CC + h * DD;
    const int row0 = w * 16 + (lane >> 2);
    const int row1 = row0 + 8;
#pragma unroll
    for (int nf = 0; nf < 8; nf++) {
        int col = nf * 8 + (lane & 3) * 2;
        *(__half2*)&yg[(size_t)row0 * CC + col] = __floats2half2_rn(o[nf][0] * inv0, o[nf][1] * inv0);
        *(__half2*)&yg[(size_t)row1 * CC + col] = __floats2half2_rn(o[nf][2] * inv1, o[nf][3] * inv1);
    }
}

// ---------------------------------------------------------------------------
// Launch
// ---------------------------------------------------------------------------
extern "C" void kernel_launch(void* const* d_in, const int* in_sizes, int n_in,
                              void* d_out, int out_size) {
    const float* x  = (const float*)d_in[0];
    const float* Wq = (const float*)d_in[1];
    const float* bq = (const float*)d_in[2];
    const float* Wk = (const float*)d_in[3];
    const float* bk = (const float*)d_in[4];
    const float* Wv = (const float*)d_in[5];
    const float* bv = (const float*)d_in[6];
    const float* Wp = (const float*)d_in[7];
    const float* bp = (const float*)d_in[8];
    float* out = (float*)d_out;

    __half *hx, *hWq, *hWk, *hWv, *hWp;
    cudaGetSymbolAddress((void**)&hx,  g_hx);
    cudaGetSymbolAddress((void**)&hWq, g_hWq);
    cudaGetSymbolAddress((void**)&hWk, g_hWk);
    cudaGetSymbolAddress((void**)&hWv, g_hWv);
    cudaGetSymbolAddress((void**)&hWp, g_hWp);

    const int nx4 = (BT * CC) / 4;     // 2M
    const int nw4 = (CC * CC) / 4;     // 256K
    f2h_kernel<<<(nx4 + 255) / 256, 256>>>((const float4*)x,  (__half2*)hx,  nx4);
    f2h_kernel<<<(nw4 + 255) / 256, 256>>>((const float4*)Wq, (__half2*)hWq, nw4);
    f2h_kernel<<<(nw4 + 255) / 256, 256>>>((const float4*)Wk, (__half2*)hWk, nw4);
    f2h_kernel<<<(nw4 + 255) / 256, 256>>>((const float4*)Wv, (__half2*)hWv, nw4);
    f2h_kernel<<<(nw4 + 255) / 256, 256>>>((const float4*)Wp, (__half2*)hWp, nw4);

    dim3 gqkv(CC / 128, BT / 128, 3);   // (8, 64, 3)
    hgemm_qkv_kernel<<<gqkv, 256>>>(bq, bk, bv);

    attn_kernel<<<dim3(TT / 64, HH, BB), 128>>>();

    dim3 gout(CC / 128, BT / 128);      // (8, 64)
    hgemm_out_kernel<<<gout, 256>>>(bp, out);
}